// round 2
// baseline (speedup 1.0000x reference)
#include <cuda_runtime.h>
#include <cuda_bf16.h>
#include <stdint.h>

#define N_POINTS 262144
#define SP_FEAT  128
#define HIDDEN   64
#define EMBED    256
#define NUM_SP   4096
#define NUM_SP2  256
#define PAD_LIMIT 64
#define CHUNK    16

// scratch (device globals: no allocation allowed)
__device__ int   g_starts[NUM_SP + 1];
__device__ float g_tok[NUM_SP * EMBED];
__device__ int   g_mask_is_i32;   // 1 if is_masked stored as int32, 0 if uint8

// ---------- packed f32x2 helpers (ptxas will not emit FFMA2 from C++) ----------
__device__ __forceinline__ unsigned long long ffma2(unsigned long long a,
                                                    unsigned long long b,
                                                    unsigned long long c) {
    unsigned long long d;
    asm("fma.rn.f32x2 %0, %1, %2, %3;" : "=l"(d) : "l"(a), "l"(b), "l"(c));
    return d;
}
__device__ __forceinline__ unsigned long long pk(float a, float b) {
    return (unsigned long long)__float_as_uint(a) |
           ((unsigned long long)__float_as_uint(b) << 32);
}
__device__ __forceinline__ float lo32(unsigned long long v) {
    return __uint_as_float((unsigned int)v);
}
__device__ __forceinline__ float hi32(unsigned long long v) {
    return __uint_as_float((unsigned int)(v >> 32));
}

// ---------- kernel A: detect is_masked dtype ----------
// Reads first 1024 int32 words (4096 bytes: in-bounds whether the buffer is
// 4096 uint8 or 4096 int32). If every word is 0/1 -> int32 layout; a
// uint8-packed bool array (60% true) is certain to have a word value > 1.
__global__ void k_detect_mask(const int* __restrict__ m) {
    __shared__ int bad;
    if (threadIdx.x == 0) bad = 0;
    __syncthreads();
    for (int i = threadIdx.x; i < 1024; i += blockDim.x) {
        unsigned int v = (unsigned int)m[i];
        if (v > 1u) atomicOr(&bad, 1);
    }
    __syncthreads();
    if (threadIdx.x == 0) g_mask_is_i32 = bad ? 0 : 1;
}

// ---------- kernel 0: segment starts via binary search (idx10 sorted, all sp non-empty) ----------
__global__ void k_seg_starts(const int* __restrict__ idx10) {
    int sp = blockIdx.x * blockDim.x + threadIdx.x;
    if (sp > NUM_SP) return;
    if (sp == NUM_SP) { g_starts[sp] = N_POINTS; return; }
    int lo = 0, hi = N_POINTS;
    while (lo < hi) {
        int mid = (lo + hi) >> 1;
        if (idx10[mid] < sp) lo = mid + 1; else hi = mid;
    }
    g_starts[sp] = lo;
}

// ---------- kernel 1: fused MLP + segment-max. one block per superpoint ----------
__global__ __launch_bounds__(256, 2)
void k_mlp(const float* __restrict__ x,
           const float* __restrict__ W1, const float* __restrict__ b1,
           const float* __restrict__ W2, const float* __restrict__ b2)
{
    __shared__ unsigned long long w1p[64 * 64];   // 32 KB
    __shared__ float xs[CHUNK * 132];             // pad 132 -> conflict-free pair reads
    __shared__ float h1s[CHUNK * 66];
    __shared__ float b1s[HIDDEN];

    const int tid = threadIdx.x;
    const int sp  = blockIdx.x;

    // --- W2 column (embed dim e = tid) packed over k into registers ---
    unsigned long long w2p[32];
    {
        const int e = tid;
        #pragma unroll
        for (int k2 = 0; k2 < 32; k2++)
            w2p[k2] = pk(W2[(2 * k2) * EMBED + e], W2[(2 * k2 + 1) * EMBED + e]);
    }
    const float b2e = b2[tid];

    // --- W1 packed over k into smem ---
    for (int i = tid; i < 64 * 64; i += 256) {
        int k2 = i >> 6, j = i & 63;
        w1p[i] = pk(W1[(2 * k2) * HIDDEN + j], W1[(2 * k2 + 1) * HIDDEN + j]);
    }
    if (tid < HIDDEN) b1s[tid] = b1[tid];

    const int s    = g_starts[sp];
    const int eend = g_starts[sp + 1];

    const int p_of_t = tid >> 4;   // 0..15 point within chunk (layer1 role)
    const int j_of_t = tid & 15;   // handles j, j+16, j+32, j+48

    float m = 0.0f;                // relu output >= 0, segment non-empty -> max >= 0

    for (int base = s; base < eend; base += CHUNK) {
        __syncthreads();  // prior layer2 readers done before xs/h1s overwrite

        // load x chunk (float4 vectorized, zero-fill past N_POINTS)
        for (int i = tid; i < CHUNK * 32; i += 256) {
            int p  = i >> 5;
            int c4 = i & 31;
            int gp = base + p;
            float4 v = (gp < N_POINTS) ? ((const float4*)x)[gp * 32 + c4]
                                       : make_float4(0.f, 0.f, 0.f, 0.f);
            ((float4*)(xs + p * 132))[c4] = v;
        }
        __syncthreads();

        // ---- layer 1: h1[p][j] = relu(x[p]·W1[:,j] + b1[j]), packed over k ----
        {
            const unsigned long long* xrow =
                (const unsigned long long*)(xs + p_of_t * 132);
            unsigned long long a0 = 0ull, a1 = 0ull, a2 = 0ull, a3 = 0ull;
            #pragma unroll
            for (int k2 = 0; k2 < 64; k2++) {
                unsigned long long xv = xrow[k2];
                a0 = ffma2(xv, w1p[k2 * 64 + j_of_t     ], a0);
                a1 = ffma2(xv, w1p[k2 * 64 + j_of_t + 16], a1);
                a2 = ffma2(xv, w1p[k2 * 64 + j_of_t + 32], a2);
                a3 = ffma2(xv, w1p[k2 * 64 + j_of_t + 48], a3);
            }
            float* hrow = h1s + p_of_t * 66;
            hrow[j_of_t     ] = fmaxf(lo32(a0) + hi32(a0) + b1s[j_of_t     ], 0.f);
            hrow[j_of_t + 16] = fmaxf(lo32(a1) + hi32(a1) + b1s[j_of_t + 16], 0.f);
            hrow[j_of_t + 32] = fmaxf(lo32(a2) + hi32(a2) + b1s[j_of_t + 32], 0.f);
            hrow[j_of_t + 48] = fmaxf(lo32(a3) + hi32(a3) + b1s[j_of_t + 48], 0.f);
        }
        __syncthreads();

        // ---- layer 2 + running max: thread = embed column e = tid ----
        const int lim = min(CHUNK, eend - base);
        #pragma unroll 1
        for (int p = 0; p < lim; p++) {
            const unsigned long long* hrow =
                (const unsigned long long*)(h1s + p * 66);
            unsigned long long acc = 0ull;
            #pragma unroll
            for (int k2 = 0; k2 < 32; k2++)
                acc = ffma2(hrow[k2], w2p[k2], acc);
            float v = fmaxf(lo32(acc) + hi32(acc) + b2e, 0.f);
            m = fmaxf(m, v);
        }
    }

    g_tok[sp * EMBED + tid] = m;
}

// ---------- kernel 2: rank within idx21 group + scatter rows ----------
__global__ void k_scatter(const int* __restrict__ idx21,
                          const void* __restrict__ is_masked,
                          float* __restrict__ out)
{
    const int sp = blockIdx.x;
    __shared__ int s_off;

    if (threadIdx.x == 0) {
        const int mode = g_mask_is_i32;
        const int* mi           = (const int*)is_masked;
        const unsigned char* mb = (const unsigned char*)is_masked;

        int g = idx21[sp];
        // group start: lower_bound(idx21, g) in [0, sp]
        int lo = 0, hi = sp;
        while (lo < hi) {
            int mid = (lo + hi) >> 1;
            if (idx21[mid] < g) lo = mid + 1; else hi = mid;
        }
        bool me = mode ? (mi[sp] != 0) : (mb[sp] != 0);
        int rank = 0;
        for (int j = lo; j < sp; j++) {
            bool fj = mode ? (mi[j] != 0) : (mb[j] != 0);
            rank += (fj == me);
        }
        int base = me ? (NUM_SP2 * PAD_LIMIT * EMBED) : 0;   // (remain, mask) order
        s_off = base + (g * PAD_LIMIT + rank) * EMBED;
    }
    __syncthreads();

    float4*       dst = (float4*)(out + s_off);
    const float4* src = (const float4*)(g_tok + sp * EMBED);
    dst[threadIdx.x] = src[threadIdx.x];   // 64 threads x float4 = 256 floats
}

// ---------- launch ----------
extern "C" void kernel_launch(void* const* d_in, const int* in_sizes, int n_in,
                              void* d_out, int out_size) {
    const float* x     = (const float*)d_in[0];
    const int*   idx10 = (const int*)d_in[1];
    const int*   idx21 = (const int*)d_in[2];
    const void*  msk   = (const void*)d_in[3];
    const float* W1    = (const float*)d_in[4];
    const float* b1    = (const float*)d_in[5];
    const float* W2    = (const float*)d_in[6];
    const float* b2    = (const float*)d_in[7];
    float* out = (float*)d_out;

    cudaMemsetAsync(out, 0, (size_t)out_size * sizeof(float));
    k_detect_mask<<<1, 256>>>((const int*)msk);
    k_seg_starts<<<(NUM_SP + 1 + 255) / 256, 256>>>(idx10);
    k_mlp<<<NUM_SP, 256>>>(x, W1, b1, W2, b2);
    k_scatter<<<NUM_SP, 64>>>(idx21, msk, out);
}

// round 4
// speedup vs baseline: 1.7661x; 1.7661x over previous
#include <cuda_runtime.h>
#include <cuda_bf16.h>
#include <stdint.h>

#define N_POINTS 262144
#define SP_FEAT  128
#define HIDDEN   64
#define EMBED    256
#define NUM_SP   4096
#define NUM_SP2  256
#define PAD_LIMIT 64
#define TILE_M   128
#define N_TILES  (N_POINTS / TILE_M)   // 2048

// ---------------- device scratch ----------------
__device__ int g_tok[NUM_SP * EMBED];          // float bits, values >= 0
__device__ int g_mask_is_i32;
__device__ __align__(16) unsigned short g_w1t_hi[64 * 128];    // W1^T, swizzled image
__device__ __align__(16) unsigned short g_w1t_lo[64 * 128];
__device__ __align__(16) unsigned short g_w2t_hi[256 * 64];    // W2^T, swizzled image
__device__ __align__(16) unsigned short g_w2t_lo[256 * 64];

// ---------------- helpers ----------------
__device__ __forceinline__ uint32_t smem_u32(const void* p) {
    uint32_t a;
    asm("{ .reg .u64 t; cvta.to.shared.u64 t, %1; cvt.u32.u64 %0, t; }" : "=r"(a) : "l"(p));
    return a;
}
// swizzled byte offset, 256B rows (k in elements of bf16, 0..127)
__device__ __forceinline__ uint32_t off256(uint32_t row, uint32_t k) {
    return row * 256u + (((k >> 3) ^ (row & 7u)) << 4) + (k & 7u) * 2u;
}
// swizzled byte offset, 128B rows (k 0..63)
__device__ __forceinline__ uint32_t off128(uint32_t row, uint32_t k) {
    return row * 128u + ((((k >> 3) ^ (row & 7u)) & 7u) << 4) + (k & 7u) * 2u;
}
__device__ __forceinline__ uint32_t pack_bf2(float a, float b) {
    __nv_bfloat162 t = __floats2bfloat162_rn(a, b);       // .x=a (low half)
    return *(uint32_t*)&t;
}
__device__ __forceinline__ void ldsm4(uint32_t r[4], uint32_t addr) {
    asm volatile("ldmatrix.sync.aligned.m8n8.x4.shared.b16 {%0,%1,%2,%3}, [%4];"
                 : "=r"(r[0]), "=r"(r[1]), "=r"(r[2]), "=r"(r[3]) : "r"(addr));
}
__device__ __forceinline__ void ldsm2(uint32_t r[2], uint32_t addr) {
    asm volatile("ldmatrix.sync.aligned.m8n8.x2.shared.b16 {%0,%1}, [%2];"
                 : "=r"(r[0]), "=r"(r[1]) : "r"(addr));
}
__device__ __forceinline__ void mma_bf16(float c[4], const uint32_t a[4], const uint32_t b[2]) {
    asm volatile("mma.sync.aligned.m16n8k16.row.col.f32.bf16.bf16.f32 "
                 "{%0,%1,%2,%3}, {%4,%5,%6,%7}, {%8,%9}, {%0,%1,%2,%3};"
                 : "+f"(c[0]), "+f"(c[1]), "+f"(c[2]), "+f"(c[3])
                 : "r"(a[0]), "r"(a[1]), "r"(a[2]), "r"(a[3]), "r"(b[0]), "r"(b[1]));
}

// ---------------- smem layout (dynamic) ----------------
#define S_XHI   0          // 128x128 bf16, 256B rows, swizzled (32768)
#define S_XLO   32768
#define S_W1HI  65536      // 64x128 bf16 (16384)
#define S_W1LO  81920
#define S_W2HI  98304      // 256x64 bf16 (32768)
#define S_W2LO  131072
#define S_HHI   163840     // 128x64 bf16 (16384)
#define S_HLO   180224
#define S_SPS   196608     // 128 ints
#define S_B1    197120     // 64 f32
#define S_B2    197376     // 256 f32
#define SMEM_TOTAL 198400

// ---------------- small kernels ----------------
__global__ void k_detect_mask(const int* __restrict__ m) {
    __shared__ int bad;
    if (threadIdx.x == 0) bad = 0;
    __syncthreads();
    for (int i = threadIdx.x; i < 1024; i += blockDim.x)
        if ((unsigned)m[i] > 1u) atomicOr(&bad, 1);
    __syncthreads();
    if (threadIdx.x == 0) g_mask_is_i32 = bad ? 0 : 1;
}

__global__ void k_zero_tok() {
    int i = blockIdx.x * blockDim.x + threadIdx.x;
    if (i < NUM_SP * EMBED) g_tok[i] = 0;
}

// Pack W1^T / W2^T into hi/lo bf16 swizzled images
__global__ void k_prep_w(const float* __restrict__ W1, const float* __restrict__ W2) {
    int i = blockIdx.x * blockDim.x + threadIdx.x;   // 16384 threads
    if (i < 64 * 128) {                              // W1t[n=64][k=128] = W1[k][n]
        int n = i >> 7, k = i & 127;
        float v = W1[k * HIDDEN + n];
        __nv_bfloat16 h = __float2bfloat16_rn(v);
        float r = v - __bfloat162float(h);
        uint32_t off = off256((uint32_t)n, (uint32_t)k);
        g_w1t_hi[off >> 1] = __bfloat16_as_ushort(h);
        g_w1t_lo[off >> 1] = __bfloat16_as_ushort(__float2bfloat16_rn(r));
    }
    if (i < 256 * 64) {                              // W2t[n=256][k=64] = W2[k][n]
        int n = i >> 6, k = i & 63;
        float v = W2[k * EMBED + n];
        __nv_bfloat16 h = __float2bfloat16_rn(v);
        float r = v - __bfloat162float(h);
        uint32_t off = off128((uint32_t)n, (uint32_t)k);
        g_w2t_hi[off >> 1] = __bfloat16_as_ushort(h);
        g_w2t_lo[off >> 1] = __bfloat16_as_ushort(__float2bfloat16_rn(r));
    }
}

// ---------------- main fused kernel: one 128-point tile per block ----------------
__global__ __launch_bounds__(256, 1)
void k_main(const float* __restrict__ x, const int* __restrict__ idx10,
            const float* __restrict__ b1, const float* __restrict__ b2)
{
    extern __shared__ char sm[];
    const uint32_t smb = smem_u32(sm);
    const int tid  = threadIdx.x;
    const int wid  = tid >> 5;
    const int lane = tid & 31;
    const int q    = lane & 3;        // col pair within fragment
    const int rb   = lane >> 2;       // row base within fragment
    const int base = blockIdx.x * TILE_M;

    // biases, sp ids
    if (tid < 64)  ((float*)(sm + S_B1))[tid] = b1[tid];
    ((float*)(sm + S_B2))[tid] = b2[tid];
    if (tid < 128) ((int*)(sm + S_SPS))[tid] = idx10[base + tid];

    // copy prepacked W images (96 KB, L2-hot)
    {
        uint4* d1h = (uint4*)(sm + S_W1HI); const uint4* s1h = (const uint4*)g_w1t_hi;
        uint4* d1l = (uint4*)(sm + S_W1LO); const uint4* s1l = (const uint4*)g_w1t_lo;
        for (int i = tid; i < 1024; i += 256) { d1h[i] = s1h[i]; d1l[i] = s1l[i]; }
        uint4* d2h = (uint4*)(sm + S_W2HI); const uint4* s2h = (const uint4*)g_w2t_hi;
        uint4* d2l = (uint4*)(sm + S_W2LO); const uint4* s2l = (const uint4*)g_w2t_lo;
        for (int i = tid; i < 2048; i += 256) { d2h[i] = s2h[i]; d2l[i] = s2l[i]; }
    }

    // x tile: load f32, split -> bf16 hi/lo, store swizzled
    for (int i = tid; i < TILE_M * 32; i += 256) {
        int p = i >> 5, c4 = i & 31;
        int k = c4 * 4;
        float4 v = ((const float4*)x)[(base + p) * 32 + c4];
        __nv_bfloat16 h0 = __float2bfloat16_rn(v.x), h1 = __float2bfloat16_rn(v.y);
        __nv_bfloat16 h2 = __float2bfloat16_rn(v.z), h3 = __float2bfloat16_rn(v.w);
        uint2 hi = make_uint2(pack_bf2(v.x, v.y), pack_bf2(v.z, v.w));
        uint2 lo = make_uint2(pack_bf2(v.x - __bfloat162float(h0), v.y - __bfloat162float(h1)),
                              pack_bf2(v.z - __bfloat162float(h2), v.w - __bfloat162float(h3)));
        uint32_t off = off256((uint32_t)p, (uint32_t)k);
        *(uint2*)(sm + S_XHI + off) = hi;
        *(uint2*)(sm + S_XLO + off) = lo;
    }
    __syncthreads();

    // cache sp ids for this thread's fragment rows (fixed across whole block)
    const int* sps = (const int*)(sm + S_SPS);
    int sprow[16];
    #pragma unroll
    for (int mt = 0; mt < 8; mt++) {
        sprow[2*mt]     = sps[16*mt + rb];
        sprow[2*mt + 1] = sps[16*mt + rb + 8];
    }

    // ================= layer 1: warp w -> cols 8w..8w+7, all 128 rows =================
    float acc[8][4];
    #pragma unroll
    for (int mt = 0; mt < 8; mt++)
        #pragma unroll
        for (int j = 0; j < 4; j++) acc[mt][j] = 0.f;

    #pragma unroll
    for (int s = 0; s < 3; s++) {
        const uint32_t Ab = smb + ((s == 1) ? S_XLO : S_XHI);
        const uint32_t Bb = smb + ((s == 2) ? S_W1LO : S_W1HI);
        // B frags: 8 k-steps, register resident
        uint32_t bf[8][2];
        #pragma unroll
        for (int ks = 0; ks < 8; ks++) {
            uint32_t addr = Bb + off256((uint32_t)(8*wid + (lane & 7)),
                                        (uint32_t)(16*ks + ((lane >> 3) & 1) * 8));
            ldsm2(bf[ks], addr);
        }
        #pragma unroll
        for (int ks = 0; ks < 8; ks++) {
            #pragma unroll
            for (int mt = 0; mt < 8; mt++) {
                uint32_t af[4];
                uint32_t addr = Ab + off256((uint32_t)(16*mt + (lane & 15)),
                                            (uint32_t)(16*ks + (lane >> 4) * 8));
                ldsm4(af, addr);
                mma_bf16(acc[mt], af, bf[ks]);
            }
        }
    }

    // epilogue 1: bias + relu -> bf16 hi/lo into smem H (swizzled)
    {
        const float* b1s = (const float*)(sm + S_B1);
        const int col = 8*wid + 2*q;
        const float bia0 = b1s[col], bia1 = b1s[col + 1];
        #pragma unroll
        for (int mt = 0; mt < 8; mt++) {
            int r1 = 16*mt + rb, r2 = r1 + 8;
            float v00 = fmaxf(acc[mt][0] + bia0, 0.f);
            float v01 = fmaxf(acc[mt][1] + bia1, 0.f);
            float v10 = fmaxf(acc[mt][2] + bia0, 0.f);
            float v11 = fmaxf(acc[mt][3] + bia1, 0.f);
            __nv_bfloat16 h00 = __float2bfloat16_rn(v00), h01 = __float2bfloat16_rn(v01);
            __nv_bfloat16 h10 = __float2bfloat16_rn(v10), h11 = __float2bfloat16_rn(v11);
            uint32_t o1 = off128((uint32_t)r1, (uint32_t)col);
            uint32_t o2 = off128((uint32_t)r2, (uint32_t)col);
            *(uint32_t*)(sm + S_HHI + o1) = pack_bf2(v00, v01);
            *(uint32_t*)(sm + S_HHI + o2) = pack_bf2(v10, v11);
            *(uint32_t*)(sm + S_HLO + o1) = pack_bf2(v00 - __bfloat162float(h00),
                                                     v01 - __bfloat162float(h01));
            *(uint32_t*)(sm + S_HLO + o2) = pack_bf2(v10 - __bfloat162float(h10),
                                                     v11 - __bfloat162float(h11));
        }
    }
    __syncthreads();

    // ================= layer 2: warp w -> cols 32w..32w+31, two 16-col halves =================
    const float* b2s = (const float*)(sm + S_B2);
    #pragma unroll 1
    for (int hf = 0; hf < 2; hf++) {
        float a2[2][8][4];
        #pragma unroll
        for (int nth = 0; nth < 2; nth++)
            #pragma unroll
            for (int mt = 0; mt < 8; mt++)
                #pragma unroll
                for (int j = 0; j < 4; j++) a2[nth][mt][j] = 0.f;

        #pragma unroll
        for (int s = 0; s < 3; s++) {
            const uint32_t Ab = smb + ((s == 1) ? S_HLO : S_HHI);
            const uint32_t Bb = smb + ((s == 2) ? S_W2LO : S_W2HI);
            uint32_t bf[2][4][2];
            #pragma unroll
            for (int nth = 0; nth < 2; nth++) {
                int n0 = 32*wid + 8*(2*hf + nth);
                #pragma unroll
                for (int ks = 0; ks < 4; ks++) {
                    uint32_t addr = Bb + off128((uint32_t)(n0 + (lane & 7)),
                                                (uint32_t)(16*ks + ((lane >> 3) & 1) * 8));
                    ldsm2(bf[nth][ks], addr);
                }
            }
            #pragma unroll
            for (int ks = 0; ks < 4; ks++) {
                #pragma unroll
                for (int mt = 0; mt < 8; mt++) {
                    uint32_t af[4];
                    uint32_t addr = Ab + off128((uint32_t)(16*mt + (lane & 15)),
                                                (uint32_t)(16*ks + (lane >> 4) * 8));
                    ldsm4(af, addr);
                    mma_bf16(a2[0][mt], af, bf[0][ks]);
                    mma_bf16(a2[1][mt], af, bf[1][ks]);
                }
            }
        }

        // epilogue 2: bias + relu + segmented max (rows strictly increasing) -> atomicMax
        #pragma unroll
        for (int nth = 0; nth < 2; nth++) {
            int colb = 32*wid + 8*(2*hf + nth) + 2*q;
            #pragma unroll
            for (int c01 = 0; c01 < 2; c01++) {
                int col = colb + c01;
                float bias = b2s[col];
                int cursp = sprow[0];
                float cur = -1.f;
                #pragma unroll
                for (int mt = 0; mt < 8; mt++) {
                    #pragma unroll
                    for (int rr = 0; rr < 2; rr++) {
                        float v = fmaxf(a2[nth][mt][c01 + 2*rr] + bias, 0.f);
                        int sp = sprow[2*mt + rr];
                        if (sp != cursp) {
                            atomicMax(&g_tok[cursp * EMBED + col], __float_as_int(cur));
                            cursp = sp; cur = v;
                        } else {
                            cur = fmaxf(cur, v);
                        }
                    }
                }
                atomicMax(&g_tok[cursp * EMBED + col], __float_as_int(cur));
            }
        }
    }
}

// ---------------- scatter (unchanged from passing R2) ----------------
__global__ void k_scatter(const int* __restrict__ idx21,
                          const void* __restrict__ is_masked,
                          float* __restrict__ out)
{
    const int sp = blockIdx.x;
    __shared__ int s_off;
    if (threadIdx.x == 0) {
        const int mode = g_mask_is_i32;
        const int* mi = (const int*)is_masked;
        const unsigned char* mb = (const unsigned char*)is_masked;
        int g = idx21[sp];
        int lo = 0, hi = sp;
        while (lo < hi) { int mid = (lo + hi) >> 1; if (idx21[mid] < g) lo = mid + 1; else hi = mid; }
        bool me = mode ? (mi[sp] != 0) : (mb[sp] != 0);
        int rank = 0;
        for (int j = lo; j < sp; j++) {
            bool fj = mode ? (mi[j] != 0) : (mb[j] != 0);
            rank += (fj == me);
        }
        int b = me ? (NUM_SP2 * PAD_LIMIT * EMBED) : 0;
        s_off = b + (g * PAD_LIMIT + rank) * EMBED;
    }
    __syncthreads();
    float4*       dst = (float4*)(out + s_off);
    const float4* src = (const float4*)((const float*)g_tok + sp * EMBED);
    dst[threadIdx.x] = src[threadIdx.x];
}

// ---------------- launch ----------------
extern "C" void kernel_launch(void* const* d_in, const int* in_sizes, int n_in,
                              void* d_out, int out_size) {
    const float* x     = (const float*)d_in[0];
    const int*   idx10 = (const int*)d_in[1];
    const int*   idx21 = (const int*)d_in[2];
    const void*  msk   = (const void*)d_in[3];
    const float* W1    = (const float*)d_in[4];
    const float* b1    = (const float*)d_in[5];
    const float* W2    = (const float*)d_in[6];
    const float* b2    = (const float*)d_in[7];
    float* out = (float*)d_out;

    cudaFuncSetAttribute(k_main, cudaFuncAttributeMaxDynamicSharedMemorySize, SMEM_TOTAL);

    cudaMemsetAsync(out, 0, (size_t)out_size * sizeof(float));
    k_detect_mask<<<1, 256>>>((const int*)msk);
    k_zero_tok<<<(NUM_SP * EMBED + 255) / 256, 256>>>();
    k_prep_w<<<64, 256>>>(W1, W2);
    k_main<<<N_TILES, 256, SMEM_TOTAL>>>(x, idx10, b1, b2);
    k_scatter<<<NUM_SP, 64>>>(idx21, msk, out);
}

// round 5
// speedup vs baseline: 2.6047x; 1.4748x over previous
#include <cuda_runtime.h>
#include <cuda_bf16.h>
#include <stdint.h>

#define N_POINTS 262144
#define SP_FEAT  128
#define HIDDEN   64
#define EMBED    256
#define NUM_SP   4096
#define NUM_SP2  256
#define PAD_LIMIT 64
#define TILE_M   128
#define N_TILES  (N_POINTS / TILE_M)   // 2048

// ---------------- device scratch ----------------
__device__ int g_tok[NUM_SP * EMBED];          // float bits, values >= 0
__device__ int g_mask_is_i32;
__device__ __align__(16) unsigned short g_w1t_hi[64 * 128];    // W1^T, swizzled image
__device__ __align__(16) unsigned short g_w1t_lo[64 * 128];
__device__ __align__(16) unsigned short g_w2t_hi[256 * 64];    // W2^T, swizzled image
__device__ __align__(16) unsigned short g_w2t_lo[256 * 64];

// ---------------- helpers ----------------
__device__ __forceinline__ uint32_t smem_u32(const void* p) {
    uint32_t a;
    asm("{ .reg .u64 t; cvta.to.shared.u64 t, %1; cvt.u32.u64 %0, t; }" : "=r"(a) : "l"(p));
    return a;
}
// swizzled byte offset, 256B rows (k in bf16 elements, 0..127)
__device__ __forceinline__ uint32_t off256(uint32_t row, uint32_t k) {
    return row * 256u + (((k >> 3) ^ (row & 7u)) << 4) + (k & 7u) * 2u;
}
// swizzled byte offset, 128B rows (k 0..63)
__device__ __forceinline__ uint32_t off128(uint32_t row, uint32_t k) {
    return row * 128u + ((((k >> 3) ^ (row & 7u)) & 7u) << 4) + (k & 7u) * 2u;
}
__device__ __forceinline__ uint32_t pack_bf2(float a, float b) {
    __nv_bfloat162 t = __floats2bfloat162_rn(a, b);       // .x=a (low half)
    return *(uint32_t*)&t;
}
__device__ __forceinline__ void ldsm4(uint32_t r[4], uint32_t addr) {
    asm volatile("ldmatrix.sync.aligned.m8n8.x4.shared.b16 {%0,%1,%2,%3}, [%4];"
                 : "=r"(r[0]), "=r"(r[1]), "=r"(r[2]), "=r"(r[3]) : "r"(addr));
}
__device__ __forceinline__ void ldsm2(uint32_t r[2], uint32_t addr) {
    asm volatile("ldmatrix.sync.aligned.m8n8.x2.shared.b16 {%0,%1}, [%2];"
                 : "=r"(r[0]), "=r"(r[1]) : "r"(addr));
}
__device__ __forceinline__ void mma_bf16(float c[4], const uint32_t a[4], const uint32_t b[2]) {
    asm volatile("mma.sync.aligned.m16n8k16.row.col.f32.bf16.bf16.f32 "
                 "{%0,%1,%2,%3}, {%4,%5,%6,%7}, {%8,%9}, {%0,%1,%2,%3};"
                 : "+f"(c[0]), "+f"(c[1]), "+f"(c[2]), "+f"(c[3])
                 : "r"(a[0]), "r"(a[1]), "r"(a[2]), "r"(a[3]), "r"(b[0]), "r"(b[1]));
}

// ---------------- smem layout (dynamic) ----------------
#define S_XHI   0          // 128x128 bf16, 256B rows, swizzled (32768)
#define S_XLO   32768
#define S_W1HI  65536      // 64x128 bf16 (16384)
#define S_W1LO  81920
#define S_W2HI  98304      // 256x64 bf16 (32768)
#define S_W2LO  131072
#define S_HHI   163840     // 128x64 bf16 (16384)
#define S_HLO   180224
#define S_SPS   196608     // 128 ints
#define S_B1    197120     // 64 f32
#define S_B2    197376     // 256 f32
#define SMEM_TOTAL 198400

// ---------------- small kernels ----------------
__global__ void k_detect_mask(const int* __restrict__ m) {
    __shared__ int bad;
    if (threadIdx.x == 0) bad = 0;
    __syncthreads();
    for (int i = threadIdx.x; i < 1024; i += blockDim.x)
        if ((unsigned)m[i] > 1u) atomicOr(&bad, 1);
    __syncthreads();
    if (threadIdx.x == 0) g_mask_is_i32 = bad ? 0 : 1;
}

__global__ void k_zero_tok() {
    int i = blockIdx.x * blockDim.x + threadIdx.x;
    if (i < NUM_SP * EMBED) g_tok[i] = 0;
}

// Pack W1^T / W2^T into hi/lo bf16 swizzled images
__global__ void k_prep_w(const float* __restrict__ W1, const float* __restrict__ W2) {
    int i = blockIdx.x * blockDim.x + threadIdx.x;   // 16384 threads
    if (i < 64 * 128) {                              // W1t[n=64][k=128] = W1[k][n]
        int n = i >> 7, k = i & 127;
        float v = W1[k * HIDDEN + n];
        __nv_bfloat16 h = __float2bfloat16_rn(v);
        float r = v - __bfloat162float(h);
        uint32_t off = off256((uint32_t)n, (uint32_t)k);
        g_w1t_hi[off >> 1] = __bfloat16_as_ushort(h);
        g_w1t_lo[off >> 1] = __bfloat16_as_ushort(__float2bfloat16_rn(r));
    }
    if (i < 256 * 64) {                              // W2t[n=256][k=64] = W2[k][n]
        int n = i >> 6, k = i & 63;
        float v = W2[k * EMBED + n];
        __nv_bfloat16 h = __float2bfloat16_rn(v);
        float r = v - __bfloat162float(h);
        uint32_t off = off128((uint32_t)n, (uint32_t)k);
        g_w2t_hi[off >> 1] = __bfloat16_as_ushort(h);
        g_w2t_lo[off >> 1] = __bfloat16_as_ushort(__float2bfloat16_rn(r));
    }
}

// ---------------- main fused kernel: one 128-point tile per block, 512 threads ----------------
__global__ __launch_bounds__(512, 1)
void k_main(const float* __restrict__ x, const int* __restrict__ idx10,
            const float* __restrict__ b1, const float* __restrict__ b2)
{
    extern __shared__ char sm[];
    const uint32_t smb = smem_u32(sm);
    const int tid  = threadIdx.x;
    const int wid  = tid >> 5;
    const int lane = tid & 31;
    const int wm   = wid & 1;         // M half: rows 64*wm .. 64*wm+63
    const int wn   = wid >> 1;        // 0..7
    const int q    = lane & 3;        // col pair within fragment
    const int rb   = lane >> 2;       // row base within fragment
    const int base = blockIdx.x * TILE_M;

    // biases, sp ids
    if (tid < 64)  ((float*)(sm + S_B1))[tid] = b1[tid];
    if (tid < 256) ((float*)(sm + S_B2))[tid] = b2[tid];
    if (tid < 128) ((int*)(sm + S_SPS))[tid] = idx10[base + tid];

    // copy prepacked W images (96 KB, L2-hot)
    {
        uint4* d1h = (uint4*)(sm + S_W1HI); const uint4* s1h = (const uint4*)g_w1t_hi;
        uint4* d1l = (uint4*)(sm + S_W1LO); const uint4* s1l = (const uint4*)g_w1t_lo;
        for (int i = tid; i < 1024; i += 512) { d1h[i] = s1h[i]; d1l[i] = s1l[i]; }
        uint4* d2h = (uint4*)(sm + S_W2HI); const uint4* s2h = (const uint4*)g_w2t_hi;
        uint4* d2l = (uint4*)(sm + S_W2LO); const uint4* s2l = (const uint4*)g_w2t_lo;
        for (int i = tid; i < 2048; i += 512) { d2h[i] = s2h[i]; d2l[i] = s2l[i]; }
    }

    // x tile: load f32, split -> bf16 hi/lo, store swizzled
    for (int i = tid; i < TILE_M * 32; i += 512) {
        int p = i >> 5, c4 = i & 31;
        int k = c4 * 4;
        float4 v = ((const float4*)x)[(base + p) * 32 + c4];
        __nv_bfloat16 h0 = __float2bfloat16_rn(v.x), h1 = __float2bfloat16_rn(v.y);
        __nv_bfloat16 h2 = __float2bfloat16_rn(v.z), h3 = __float2bfloat16_rn(v.w);
        uint2 hi = make_uint2(pack_bf2(v.x, v.y), pack_bf2(v.z, v.w));
        uint2 lo = make_uint2(pack_bf2(v.x - __bfloat162float(h0), v.y - __bfloat162float(h1)),
                              pack_bf2(v.z - __bfloat162float(h2), v.w - __bfloat162float(h3)));
        uint32_t off = off256((uint32_t)p, (uint32_t)k);
        *(uint2*)(sm + S_XHI + off) = hi;
        *(uint2*)(sm + S_XLO + off) = lo;
    }
    __syncthreads();

    // ================= layer 1: warp (wm,wn) -> rows 64wm+, cols 8wn..8wn+7 =================
    float acc[4][4];
    #pragma unroll
    for (int mt = 0; mt < 4; mt++)
        #pragma unroll
        for (int j = 0; j < 4; j++) acc[mt][j] = 0.f;

    {
        // B frags (hi & lo), register resident: 8 ks x 2 regs x 2 = 32 regs
        uint32_t bh[8][2], bl[8][2];
        #pragma unroll
        for (int ks = 0; ks < 8; ks++) {
            uint32_t o = off256((uint32_t)(8*wn + (lane & 7)),
                                (uint32_t)(16*ks + ((lane >> 3) & 1) * 8));
            ldsm2(bh[ks], smb + S_W1HI + o);
            ldsm2(bl[ks], smb + S_W1LO + o);
        }
        #pragma unroll
        for (int ks = 0; ks < 8; ks++) {
            #pragma unroll
            for (int mt = 0; mt < 4; mt++) {
                uint32_t o = off256((uint32_t)(64*wm + 16*mt + (lane & 15)),
                                    (uint32_t)(16*ks + (lane >> 4) * 8));
                uint32_t ah[4], al[4];
                ldsm4(ah, smb + S_XHI + o);
                ldsm4(al, smb + S_XLO + o);
                mma_bf16(acc[mt], ah, bh[ks]);   // hi*hi
                mma_bf16(acc[mt], al, bh[ks]);   // lo*hi
                mma_bf16(acc[mt], ah, bl[ks]);   // hi*lo
            }
        }
    }

    // epilogue 1: bias + relu -> bf16 hi/lo into smem H (swizzled)
    {
        const float* b1s = (const float*)(sm + S_B1);
        const int col = 8*wn + 2*q;
        const float bia0 = b1s[col], bia1 = b1s[col + 1];
        #pragma unroll
        for (int mt = 0; mt < 4; mt++) {
            int r1 = 64*wm + 16*mt + rb, r2 = r1 + 8;
            float v00 = fmaxf(acc[mt][0] + bia0, 0.f);
            float v01 = fmaxf(acc[mt][1] + bia1, 0.f);
            float v10 = fmaxf(acc[mt][2] + bia0, 0.f);
            float v11 = fmaxf(acc[mt][3] + bia1, 0.f);
            __nv_bfloat16 h00 = __float2bfloat16_rn(v00), h01 = __float2bfloat16_rn(v01);
            __nv_bfloat16 h10 = __float2bfloat16_rn(v10), h11 = __float2bfloat16_rn(v11);
            uint32_t o1 = off128((uint32_t)r1, (uint32_t)col);
            uint32_t o2 = off128((uint32_t)r2, (uint32_t)col);
            *(uint32_t*)(sm + S_HHI + o1) = pack_bf2(v00, v01);
            *(uint32_t*)(sm + S_HHI + o2) = pack_bf2(v10, v11);
            *(uint32_t*)(sm + S_HLO + o1) = pack_bf2(v00 - __bfloat162float(h00),
                                                     v01 - __bfloat162float(h01));
            *(uint32_t*)(sm + S_HLO + o2) = pack_bf2(v10 - __bfloat162float(h10),
                                                     v11 - __bfloat162float(h11));
        }
    }
    __syncthreads();

    // sp ids of this thread's fragment rows (warp's 64-row half)
    const int* sps = (const int*)(sm + S_SPS);
    int sprow[8];
    #pragma unroll
    for (int mt = 0; mt < 4; mt++) {
        sprow[2*mt]     = sps[64*wm + 16*mt + rb];
        sprow[2*mt + 1] = sps[64*wm + 16*mt + rb + 8];
    }

    // ================= layer 2: warp -> rows 64wm+, cols 32wn..32wn+31 (two 16-col halves) =================
    const float* b2s = (const float*)(sm + S_B2);
    #pragma unroll 1
    for (int hf = 0; hf < 2; hf++) {
        float a2[2][4][4];
        #pragma unroll
        for (int nth = 0; nth < 2; nth++)
            #pragma unroll
            for (int mt = 0; mt < 4; mt++)
                #pragma unroll
                for (int j = 0; j < 4; j++) a2[nth][mt][j] = 0.f;

        uint32_t bh[2][4][2], bl[2][4][2];
        #pragma unroll
        for (int nth = 0; nth < 2; nth++) {
            int n0 = 32*wn + 8*(2*hf + nth);
            #pragma unroll
            for (int ks = 0; ks < 4; ks++) {
                uint32_t o = off128((uint32_t)(n0 + (lane & 7)),
                                    (uint32_t)(16*ks + ((lane >> 3) & 1) * 8));
                ldsm2(bh[nth][ks], smb + S_W2HI + o);
                ldsm2(bl[nth][ks], smb + S_W2LO + o);
            }
        }
        #pragma unroll
        for (int ks = 0; ks < 4; ks++) {
            #pragma unroll
            for (int mt = 0; mt < 4; mt++) {
                uint32_t o = off128((uint32_t)(64*wm + 16*mt + (lane & 15)),
                                    (uint32_t)(16*ks + (lane >> 4) * 8));
                uint32_t ah[4], al[4];
                ldsm4(ah, smb + S_HHI + o);
                ldsm4(al, smb + S_HLO + o);
                #pragma unroll
                for (int nth = 0; nth < 2; nth++) {
                    mma_bf16(a2[nth][mt], ah, bh[nth][ks]);
                    mma_bf16(a2[nth][mt], al, bh[nth][ks]);
                    mma_bf16(a2[nth][mt], ah, bl[nth][ks]);
                }
            }
        }

        // epilogue 2: bias + relu + segmented max (rows strictly increasing) -> atomicMax
        #pragma unroll
        for (int nth = 0; nth < 2; nth++) {
            int colb = 32*wn + 8*(2*hf + nth) + 2*q;
            #pragma unroll
            for (int c01 = 0; c01 < 2; c01++) {
                int col = colb + c01;
                float bias = b2s[col];
                int cursp = sprow[0];
                float cur = -1.f;
                #pragma unroll
                for (int mt = 0; mt < 4; mt++) {
                    #pragma unroll
                    for (int rr = 0; rr < 2; rr++) {
                        float v = fmaxf(a2[nth][mt][c01 + 2*rr] + bias, 0.f);
                        int sp = sprow[2*mt + rr];
                        if (sp != cursp) {
                            atomicMax(&g_tok[cursp * EMBED + col], __float_as_int(cur));
                            cursp = sp; cur = v;
                        } else {
                            cur = fmaxf(cur, v);
                        }
                    }
                }
                atomicMax(&g_tok[cursp * EMBED + col], __float_as_int(cur));
            }
        }
    }
}

// ---------------- scatter ----------------
__global__ void k_scatter(const int* __restrict__ idx21,
                          const void* __restrict__ is_masked,
                          float* __restrict__ out)
{
    const int sp = blockIdx.x;
    __shared__ int s_off;
    if (threadIdx.x == 0) {
        const int mode = g_mask_is_i32;
        const int* mi = (const int*)is_masked;
        const unsigned char* mb = (const unsigned char*)is_masked;
        int g = idx21[sp];
        int lo = 0, hi = sp;
        while (lo < hi) { int mid = (lo + hi) >> 1; if (idx21[mid] < g) lo = mid + 1; else hi = mid; }
        bool me = mode ? (mi[sp] != 0) : (mb[sp] != 0);
        int rank = 0;
        for (int j = lo; j < sp; j++) {
            bool fj = mode ? (mi[j] != 0) : (mb[j] != 0);
            rank += (fj == me);
        }
        int b = me ? (NUM_SP2 * PAD_LIMIT * EMBED) : 0;
        s_off = b + (g * PAD_LIMIT + rank) * EMBED;
    }
    __syncthreads();
    float4*       dst = (float4*)(out + s_off);
    const float4* src = (const float4*)((const float*)g_tok + sp * EMBED);
    dst[threadIdx.x] = src[threadIdx.x];
}

// ---------------- launch ----------------
extern "C" void kernel_launch(void* const* d_in, const int* in_sizes, int n_in,
                              void* d_out, int out_size) {
    const float* x     = (const float*)d_in[0];
    const int*   idx10 = (const int*)d_in[1];
    const int*   idx21 = (const int*)d_in[2];
    const void*  msk   = (const void*)d_in[3];
    const float* W1    = (const float*)d_in[4];
    const float* b1    = (const float*)d_in[5];
    const float* W2    = (const float*)d_in[6];
    const float* b2    = (const float*)d_in[7];
    float* out = (float*)d_out;

    cudaFuncSetAttribute(k_main, cudaFuncAttributeMaxDynamicSharedMemorySize, SMEM_TOTAL);

    cudaMemsetAsync(out, 0, (size_t)out_size * sizeof(float));
    k_detect_mask<<<1, 256>>>((const int*)msk);
    k_zero_tok<<<(NUM_SP * EMBED + 255) / 256, 256>>>();
    k_prep_w<<<64, 256>>>(W1, W2);
    k_main<<<N_TILES, 512, SMEM_TOTAL>>>(x, idx10, b1, b2);
    k_scatter<<<NUM_SP, 64>>>(idx21, msk, out);
}

// round 6
// speedup vs baseline: 2.7485x; 1.0552x over previous
#include <cuda_runtime.h>
#include <cuda_bf16.h>
#include <stdint.h>

#define N_POINTS 262144
#define SP_FEAT  128
#define HIDDEN   64
#define EMBED    256
#define NUM_SP   4096
#define NUM_SP2  256
#define PAD_LIMIT 64
#define TILE_M   128
#define N_TILES  (N_POINTS / TILE_M)   // 2048

// ---------------- device scratch ----------------
__device__ int g_tok[NUM_SP * EMBED];          // float bits, values >= 0
__device__ int g_mask_is_i32;
// prepacked B fragments (mma.m16n8k16 layout), uint4 = {hi_reg0, hi_reg1, lo_reg0, lo_reg1}
__device__ __align__(16) uint4 g_w1f[4 * 2 * 8 * 32];   // [wn][nth][ks][lane]  (8 KB)
__device__ __align__(16) uint4 g_w2f[4 * 8 * 4 * 32];   // [wn][nt(hf*4+nth)][ks][lane] (64 KB)

// ---------------- helpers ----------------
__device__ __forceinline__ uint32_t smem_u32(const void* p) {
    uint32_t a;
    asm("{ .reg .u64 t; cvta.to.shared.u64 t, %1; cvt.u32.u64 %0, t; }" : "=r"(a) : "l"(p));
    return a;
}
// swizzled byte offset, 256B rows (k in bf16 elements, 0..127)
__device__ __forceinline__ uint32_t off256(uint32_t row, uint32_t k) {
    return row * 256u + (((k >> 3) ^ (row & 7u)) << 4) + (k & 7u) * 2u;
}
// swizzled byte offset, 128B rows (k 0..63)
__device__ __forceinline__ uint32_t off128(uint32_t row, uint32_t k) {
    return row * 128u + ((((k >> 3) ^ (row & 7u)) & 7u) << 4) + (k & 7u) * 2u;
}
__device__ __forceinline__ uint32_t pack_bf2(float a, float b) {
    __nv_bfloat162 t = __floats2bfloat162_rn(a, b);       // .x=a (low half)
    return *(uint32_t*)&t;
}
__device__ __forceinline__ void ldsm4(uint32_t r[4], uint32_t addr) {
    asm volatile("ldmatrix.sync.aligned.m8n8.x4.shared.b16 {%0,%1,%2,%3}, [%4];"
                 : "=r"(r[0]), "=r"(r[1]), "=r"(r[2]), "=r"(r[3]) : "r"(addr));
}
__device__ __forceinline__ void mma_bf16(float c[4], const uint32_t a[4],
                                         uint32_t b0, uint32_t b1) {
    asm volatile("mma.sync.aligned.m16n8k16.row.col.f32.bf16.bf16.f32 "
                 "{%0,%1,%2,%3}, {%4,%5,%6,%7}, {%8,%9}, {%0,%1,%2,%3};"
                 : "+f"(c[0]), "+f"(c[1]), "+f"(c[2]), "+f"(c[3])
                 : "r"(a[0]), "r"(a[1]), "r"(a[2]), "r"(a[3]), "r"(b0), "r"(b1));
}

// ---------------- smem layout (dynamic) ----------------
#define S_XHI   0          // 128x128 bf16, 256B rows, swizzled (32768)
#define S_XLO   32768
#define S_HHI   65536      // 128x64 bf16, 128B rows, swizzled (16384)
#define S_HLO   81920
#define S_SPS   98304      // 128 ints
#define S_B1    98816      // 64 f32
#define S_B2    99072      // 256 f32
#define SMEM_TOTAL 100096

// ---------------- small kernels ----------------
__global__ void k_detect_mask(const int* __restrict__ m) {
    __shared__ int bad;
    if (threadIdx.x == 0) bad = 0;
    __syncthreads();
    for (int i = threadIdx.x; i < 1024; i += blockDim.x)
        if ((unsigned)m[i] > 1u) atomicOr(&bad, 1);
    __syncthreads();
    if (threadIdx.x == 0) g_mask_is_i32 = bad ? 0 : 1;
}

__global__ void k_zero_tok() {
    int i = blockIdx.x * blockDim.x + threadIdx.x;
    if (i < NUM_SP * EMBED) g_tok[i] = 0;
}

// Prepack B fragments: exact mma.m16n8k16 B-operand per-lane words.
// reg0 holds B[k0 + 2*(lane%4) + {0,1}][n0 + lane/4], reg1 same with k0+8.
__global__ void k_prep_w(const float* __restrict__ W1, const float* __restrict__ W2) {
    int i = blockIdx.x * blockDim.x + threadIdx.x;     // 8192 threads
    if (i < 2048) {                                     // layer1: [4wn][2nth][8ks][32lane]
        int lane = i & 31, ks = (i >> 5) & 7, nth = (i >> 8) & 1, wn = i >> 9;
        int n  = 16 * wn + 8 * nth + (lane >> 2);
        int k0 = 16 * ks + 2 * (lane & 3);
        float v00 = W1[k0 * HIDDEN + n],       v01 = W1[(k0 + 1) * HIDDEN + n];
        float v10 = W1[(k0 + 8) * HIDDEN + n], v11 = W1[(k0 + 9) * HIDDEN + n];
        __nv_bfloat16 h00 = __float2bfloat16_rn(v00), h01 = __float2bfloat16_rn(v01);
        __nv_bfloat16 h10 = __float2bfloat16_rn(v10), h11 = __float2bfloat16_rn(v11);
        uint4 f;
        f.x = pack_bf2(v00, v01);
        f.y = pack_bf2(v10, v11);
        f.z = pack_bf2(v00 - __bfloat162float(h00), v01 - __bfloat162float(h01));
        f.w = pack_bf2(v10 - __bfloat162float(h10), v11 - __bfloat162float(h11));
        g_w1f[i] = f;
    } else if (i < 2048 + 4096) {                       // layer2: [4wn][8nt][4ks][32lane]
        int j = i - 2048;
        int lane = j & 31, ks = (j >> 5) & 3, nt = (j >> 7) & 7, wn = j >> 10;
        int n  = 64 * wn + 8 * nt + (lane >> 2);
        int k0 = 16 * ks + 2 * (lane & 3);
        float v00 = W2[k0 * EMBED + n],       v01 = W2[(k0 + 1) * EMBED + n];
        float v10 = W2[(k0 + 8) * EMBED + n], v11 = W2[(k0 + 9) * EMBED + n];
        __nv_bfloat16 h00 = __float2bfloat16_rn(v00), h01 = __float2bfloat16_rn(v01);
        __nv_bfloat16 h10 = __float2bfloat16_rn(v10), h11 = __float2bfloat16_rn(v11);
        uint4 f;
        f.x = pack_bf2(v00, v01);
        f.y = pack_bf2(v10, v11);
        f.z = pack_bf2(v00 - __bfloat162float(h00), v01 - __bfloat162float(h01));
        f.w = pack_bf2(v10 - __bfloat162float(h10), v11 - __bfloat162float(h11));
        g_w2f[j] = f;
    }
}

// ---------------- main fused kernel: one 128-point tile per block, 512 threads ----------------
// warp = (wm 0..3, wn 0..3): rows 32wm..+31; layer1 cols 16wn..+15; layer2 cols 64wn..+63
__global__ __launch_bounds__(512, 1)
void k_main(const float* __restrict__ x, const int* __restrict__ idx10,
            const float* __restrict__ b1, const float* __restrict__ b2)
{
    extern __shared__ char sm[];
    const uint32_t smb = smem_u32(sm);
    const int tid  = threadIdx.x;
    const int wid  = tid >> 5;
    const int lane = tid & 31;
    const int wm   = wid & 3;         // rows 32*wm..32*wm+31
    const int wn   = wid >> 2;        // 0..3
    const int q    = lane & 3;        // col pair within fragment
    const int rb   = lane >> 2;       // row base within fragment
    const int base = blockIdx.x * TILE_M;

    // biases, sp ids
    if (tid < 64)  ((float*)(sm + S_B1))[tid] = b1[tid];
    if (tid < 256) ((float*)(sm + S_B2))[tid] = b2[tid];
    if (tid < 128) ((int*)(sm + S_SPS))[tid] = idx10[base + tid];

    // B fragments for layer 1 (register resident, L2-broadcast loads)
    uint4 b1f[2][8];
    #pragma unroll
    for (int nth = 0; nth < 2; nth++)
        #pragma unroll
        for (int ks = 0; ks < 8; ks++)
            b1f[nth][ks] = g_w1f[(((wn << 1) | nth) << 8) + (ks << 5) + lane];

    // x tile: load f32, split -> bf16 hi/lo, store swizzled
    for (int i = tid; i < TILE_M * 32; i += 512) {
        int p = i >> 5, c4 = i & 31;
        int k = c4 * 4;
        float4 v = ((const float4*)x)[(base + p) * 32 + c4];
        __nv_bfloat16 h0 = __float2bfloat16_rn(v.x), h1 = __float2bfloat16_rn(v.y);
        __nv_bfloat16 h2 = __float2bfloat16_rn(v.z), h3 = __float2bfloat16_rn(v.w);
        uint2 hi = make_uint2(pack_bf2(v.x, v.y), pack_bf2(v.z, v.w));
        uint2 lo = make_uint2(pack_bf2(v.x - __bfloat162float(h0), v.y - __bfloat162float(h1)),
                              pack_bf2(v.z - __bfloat162float(h2), v.w - __bfloat162float(h3)));
        uint32_t off = off256((uint32_t)p, (uint32_t)k);
        *(uint2*)(sm + S_XHI + off) = hi;
        *(uint2*)(sm + S_XLO + off) = lo;
    }
    __syncthreads();

    // ================= layer 1 =================
    float acc[2][2][4];   // [mt][nth][4]
    #pragma unroll
    for (int mt = 0; mt < 2; mt++)
        #pragma unroll
        for (int nth = 0; nth < 2; nth++)
            #pragma unroll
            for (int j = 0; j < 4; j++) acc[mt][nth][j] = 0.f;

    #pragma unroll
    for (int ks = 0; ks < 8; ks++) {
        #pragma unroll
        for (int mt = 0; mt < 2; mt++) {
            uint32_t o = off256((uint32_t)(32*wm + 16*mt + (lane & 15)),
                                (uint32_t)(16*ks + (lane >> 4) * 8));
            uint32_t ah[4], al[4];
            ldsm4(ah, smb + S_XHI + o);
            ldsm4(al, smb + S_XLO + o);
            #pragma unroll
            for (int nth = 0; nth < 2; nth++) {
                const uint4 f = b1f[nth][ks];
                mma_bf16(acc[mt][nth], ah, f.x, f.y);   // hi*hi
                mma_bf16(acc[mt][nth], al, f.x, f.y);   // lo*hi
                mma_bf16(acc[mt][nth], ah, f.z, f.w);   // hi*lo
            }
        }
    }

    // epilogue 1: bias + relu -> bf16 hi/lo into smem H (swizzled)
    {
        const float* b1s = (const float*)(sm + S_B1);
        #pragma unroll
        for (int nth = 0; nth < 2; nth++) {
            const int col = 16*wn + 8*nth + 2*q;
            const float bia0 = b1s[col], bia1 = b1s[col + 1];
            #pragma unroll
            for (int mt = 0; mt < 2; mt++) {
                int r1 = 32*wm + 16*mt + rb, r2 = r1 + 8;
                float v00 = fmaxf(acc[mt][nth][0] + bia0, 0.f);
                float v01 = fmaxf(acc[mt][nth][1] + bia1, 0.f);
                float v10 = fmaxf(acc[mt][nth][2] + bia0, 0.f);
                float v11 = fmaxf(acc[mt][nth][3] + bia1, 0.f);
                __nv_bfloat16 h00 = __float2bfloat16_rn(v00), h01 = __float2bfloat16_rn(v01);
                __nv_bfloat16 h10 = __float2bfloat16_rn(v10), h11 = __float2bfloat16_rn(v11);
                uint32_t o1 = off128((uint32_t)r1, (uint32_t)col);
                uint32_t o2 = off128((uint32_t)r2, (uint32_t)col);
                *(uint32_t*)(sm + S_HHI + o1) = pack_bf2(v00, v01);
                *(uint32_t*)(sm + S_HHI + o2) = pack_bf2(v10, v11);
                *(uint32_t*)(sm + S_HLO + o1) = pack_bf2(v00 - __bfloat162float(h00),
                                                         v01 - __bfloat162float(h01));
                *(uint32_t*)(sm + S_HLO + o2) = pack_bf2(v10 - __bfloat162float(h10),
                                                         v11 - __bfloat162float(h11));
            }
        }
    }
    __syncthreads();

    // sp ids of this thread's fragment rows (warp's 32-row quarter)
    const int* sps = (const int*)(sm + S_SPS);
    int sprow[4];
    #pragma unroll
    for (int mt = 0; mt < 2; mt++) {
        sprow[2*mt]     = sps[32*wm + 16*mt + rb];
        sprow[2*mt + 1] = sps[32*wm + 16*mt + rb + 8];
    }

    // ================= layer 2: cols 64wn..+63, two 32-col halves =================
    const float* b2s = (const float*)(sm + S_B2);
    #pragma unroll 1
    for (int hf = 0; hf < 2; hf++) {
        // B frags for this half (L2-broadcast)
        uint4 b2f[4][4];   // [nth][ks]
        #pragma unroll
        for (int nth = 0; nth < 4; nth++)
            #pragma unroll
            for (int ks = 0; ks < 4; ks++)
                b2f[nth][ks] = g_w2f[((wn*8 + hf*4 + nth) << 7) + (ks << 5) + lane];

        float a2[4][2][4];   // [nth][mt][4]
        #pragma unroll
        for (int nth = 0; nth < 4; nth++)
            #pragma unroll
            for (int mt = 0; mt < 2; mt++)
                #pragma unroll
                for (int j = 0; j < 4; j++) a2[nth][mt][j] = 0.f;

        #pragma unroll
        for (int ks = 0; ks < 4; ks++) {
            #pragma unroll
            for (int mt = 0; mt < 2; mt++) {
                uint32_t o = off128((uint32_t)(32*wm + 16*mt + (lane & 15)),
                                    (uint32_t)(16*ks + (lane >> 4) * 8));
                uint32_t ah[4], al[4];
                ldsm4(ah, smb + S_HHI + o);
                ldsm4(al, smb + S_HLO + o);
                #pragma unroll
                for (int nth = 0; nth < 4; nth++) {
                    const uint4 f = b2f[nth][ks];
                    mma_bf16(a2[nth][mt], ah, f.x, f.y);
                    mma_bf16(a2[nth][mt], al, f.x, f.y);
                    mma_bf16(a2[nth][mt], ah, f.z, f.w);
                }
            }
        }

        // epilogue 2: bias + relu + segmented max (rows strictly increasing) -> atomicMax
        #pragma unroll
        for (int nth = 0; nth < 4; nth++) {
            int colb = 64*wn + 8*(4*hf + nth) + 2*q;
            #pragma unroll
            for (int c01 = 0; c01 < 2; c01++) {
                int col = colb + c01;
                float bias = b2s[col];
                int cursp = sprow[0];
                float cur = -1.f;
                #pragma unroll
                for (int mt = 0; mt < 2; mt++) {
                    #pragma unroll
                    for (int rr = 0; rr < 2; rr++) {
                        float v = fmaxf(a2[nth][mt][c01 + 2*rr] + bias, 0.f);
                        int sp = sprow[2*mt + rr];
                        if (sp != cursp) {
                            atomicMax(&g_tok[cursp * EMBED + col], __float_as_int(cur));
                            cursp = sp; cur = v;
                        } else {
                            cur = fmaxf(cur, v);
                        }
                    }
                }
                atomicMax(&g_tok[cursp * EMBED + col], __float_as_int(cur));
            }
        }
    }
}

// ---------------- scatter ----------------
__global__ void k_scatter(const int* __restrict__ idx21,
                          const void* __restrict__ is_masked,
                          float* __restrict__ out)
{
    const int sp = blockIdx.x;
    __shared__ int s_off;
    if (threadIdx.x == 0) {
        const int mode = g_mask_is_i32;
        const int* mi = (const int*)is_masked;
        const unsigned char* mb = (const unsigned char*)is_masked;
        int g = idx21[sp];
        int lo = 0, hi = sp;
        while (lo < hi) { int mid = (lo + hi) >> 1; if (idx21[mid] < g) lo = mid + 1; else hi = mid; }
        bool me = mode ? (mi[sp] != 0) : (mb[sp] != 0);
        int rank = 0;
        for (int j = lo; j < sp; j++) {
            bool fj = mode ? (mi[j] != 0) : (mb[j] != 0);
            rank += (fj == me);
        }
        int b = me ? (NUM_SP2 * PAD_LIMIT * EMBED) : 0;
        s_off = b + (g * PAD_LIMIT + rank) * EMBED;
    }
    __syncthreads();
    float4*       dst = (float4*)(out + s_off);
    const float4* src = (const float4*)((const float*)g_tok + sp * EMBED);
    dst[threadIdx.x] = src[threadIdx.x];
}

// ---------------- launch ----------------
extern "C" void kernel_launch(void* const* d_in, const int* in_sizes, int n_in,
                              void* d_out, int out_size) {
    const float* x     = (const float*)d_in[0];
    const int*   idx10 = (const int*)d_in[1];
    const int*   idx21 = (const int*)d_in[2];
    const void*  msk   = (const void*)d_in[3];
    const float* W1    = (const float*)d_in[4];
    const float* b1    = (const float*)d_in[5];
    const float* W2    = (const float*)d_in[6];
    const float* b2    = (const float*)d_in[7];
    float* out = (float*)d_out;

    cudaFuncSetAttribute(k_main, cudaFuncAttributeMaxDynamicSharedMemorySize, SMEM_TOTAL);

    cudaMemsetAsync(out, 0, (size_t)out_size * sizeof(float));
    k_detect_mask<<<1, 256>>>((const int*)msk);
    k_zero_tok<<<(NUM_SP * EMBED + 255) / 256, 256>>>();
    k_prep_w<<<32, 256>>>(W1, W2);
    k_main<<<N_TILES, 512, SMEM_TOTAL>>>(x, idx10, b1, b2);
    k_scatter<<<NUM_SP, 64>>>(idx21, msk, out);
}

// round 7
// speedup vs baseline: 2.9763x; 1.0829x over previous
#include <cuda_runtime.h>
#include <cuda_bf16.h>
#include <stdint.h>

#define N_POINTS 262144
#define SP_FEAT  128
#define HIDDEN   64
#define EMBED    256
#define NUM_SP   4096
#define NUM_SP2  256
#define PAD_LIMIT 64
#define TILE_M   128
#define N_TILES  (N_POINTS / TILE_M)   // 2048

// ---------------- device scratch ----------------
__device__ int g_tok[NUM_SP * EMBED];          // float bits, values >= 0
__device__ int g_mask_is_i32;
// prepacked B fragments (mma.m16n8k16 layout), uint4 = {hi_reg0, hi_reg1, lo_reg0, lo_reg1}
__device__ __align__(16) uint4 g_w1f[4 * 2 * 8 * 32];   // [wn][nth][ks][lane]  (8 KB)
__device__ __align__(16) uint4 g_w2f[4 * 8 * 4 * 32];   // [wn][nt][ks][lane]   (64 KB)

// ---------------- helpers ----------------
__device__ __forceinline__ uint32_t smem_u32(const void* p) {
    uint32_t a;
    asm("{ .reg .u64 t; cvta.to.shared.u64 t, %1; cvt.u32.u64 %0, t; }" : "=r"(a) : "l"(p));
    return a;
}
// swizzled byte offset, 256B rows (k in bf16 elements, 0..127)
__device__ __forceinline__ uint32_t off256(uint32_t row, uint32_t k) {
    return row * 256u + (((k >> 3) ^ (row & 7u)) << 4) + (k & 7u) * 2u;
}
// swizzled byte offset, 128B rows (k 0..63)
__device__ __forceinline__ uint32_t off128(uint32_t row, uint32_t k) {
    return row * 128u + ((((k >> 3) ^ (row & 7u)) & 7u) << 4) + (k & 7u) * 2u;
}
__device__ __forceinline__ uint32_t pack_bf2(float a, float b) {
    __nv_bfloat162 t = __floats2bfloat162_rn(a, b);       // .x=a (low half)
    return *(uint32_t*)&t;
}
__device__ __forceinline__ void ldsm4(uint32_t r[4], uint32_t addr) {
    asm volatile("ldmatrix.sync.aligned.m8n8.x4.shared.b16 {%0,%1,%2,%3}, [%4];"
                 : "=r"(r[0]), "=r"(r[1]), "=r"(r[2]), "=r"(r[3]) : "r"(addr));
}
__device__ __forceinline__ void mma_bf16(float c[4], const uint32_t a[4],
                                         uint32_t b0, uint32_t b1) {
    asm volatile("mma.sync.aligned.m16n8k16.row.col.f32.bf16.bf16.f32 "
                 "{%0,%1,%2,%3}, {%4,%5,%6,%7}, {%8,%9}, {%0,%1,%2,%3};"
                 : "+f"(c[0]), "+f"(c[1]), "+f"(c[2]), "+f"(c[3])
                 : "r"(a[0]), "r"(a[1]), "r"(a[2]), "r"(a[3]), "r"(b0), "r"(b1));
}

// ---------------- smem layout (dynamic) ----------------
#define S_XHI   0          // 128x128 bf16, 256B rows, swizzled (32768)
#define S_XLO   32768
#define S_HHI   65536      // 128x64 bf16, 128B rows, swizzled (16384)
#define S_HLO   81920
#define S_SPS   98304      // 128 ints
#define S_B1    98816      // 64 f32
#define S_B2    99072      // 256 f32
#define SMEM_TOTAL 100096

// ---------------- small kernels ----------------
__global__ void k_zero_tok() {
    int i = blockIdx.x * blockDim.x + threadIdx.x;
    if (i < NUM_SP * EMBED) g_tok[i] = 0;
}

// Prepack B fragments + detect is_masked dtype (block 0).
__global__ void k_prep_w(const float* __restrict__ W1, const float* __restrict__ W2,
                         const int* __restrict__ msk) {
    int i = blockIdx.x * blockDim.x + threadIdx.x;     // 8192 threads
    if (blockIdx.x == 0) {
        __shared__ int bad;
        if (threadIdx.x == 0) bad = 0;
        __syncthreads();
        for (int j = threadIdx.x; j < 1024; j += blockDim.x)
            if ((unsigned)msk[j] > 1u) atomicOr(&bad, 1);
        __syncthreads();
        if (threadIdx.x == 0) g_mask_is_i32 = bad ? 0 : 1;
    }
    if (i < 2048) {                                     // layer1: [4wn][2nth][8ks][32lane]
        int lane = i & 31, ks = (i >> 5) & 7, nth = (i >> 8) & 1, wn = i >> 9;
        int n  = 16 * wn + 8 * nth + (lane >> 2);
        int k0 = 16 * ks + 2 * (lane & 3);
        float v00 = W1[k0 * HIDDEN + n],       v01 = W1[(k0 + 1) * HIDDEN + n];
        float v10 = W1[(k0 + 8) * HIDDEN + n], v11 = W1[(k0 + 9) * HIDDEN + n];
        __nv_bfloat16 h00 = __float2bfloat16_rn(v00), h01 = __float2bfloat16_rn(v01);
        __nv_bfloat16 h10 = __float2bfloat16_rn(v10), h11 = __float2bfloat16_rn(v11);
        uint4 f;
        f.x = pack_bf2(v00, v01);
        f.y = pack_bf2(v10, v11);
        f.z = pack_bf2(v00 - __bfloat162float(h00), v01 - __bfloat162float(h01));
        f.w = pack_bf2(v10 - __bfloat162float(h10), v11 - __bfloat162float(h11));
        g_w1f[i] = f;
    } else if (i < 2048 + 4096) {                       // layer2: [4wn][8nt][4ks][32lane]
        int j = i - 2048;
        int lane = j & 31, ks = (j >> 5) & 3, nt = (j >> 7) & 7, wn = j >> 10;
        int n  = 64 * wn + 8 * nt + (lane >> 2);
        int k0 = 16 * ks + 2 * (lane & 3);
        float v00 = W2[k0 * EMBED + n],       v01 = W2[(k0 + 1) * EMBED + n];
        float v10 = W2[(k0 + 8) * EMBED + n], v11 = W2[(k0 + 9) * EMBED + n];
        __nv_bfloat16 h00 = __float2bfloat16_rn(v00), h01 = __float2bfloat16_rn(v01);
        __nv_bfloat16 h10 = __float2bfloat16_rn(v10), h11 = __float2bfloat16_rn(v11);
        uint4 f;
        f.x = pack_bf2(v00, v01);
        f.y = pack_bf2(v10, v11);
        f.z = pack_bf2(v00 - __bfloat162float(h00), v01 - __bfloat162float(h01));
        f.w = pack_bf2(v10 - __bfloat162float(h10), v11 - __bfloat162float(h11));
        g_w2f[j] = f;
    }
}

// ---------------- main fused kernel: one 128-point tile per block, 512 threads ----------------
// warp = (wm 0..3, wn 0..3): rows 32wm..+31; layer1 cols 16wn..+15; layer2 cols 64wn..+63
__global__ __launch_bounds__(512, 1)
void k_main(const float* __restrict__ x, const int* __restrict__ idx10,
            const float* __restrict__ b1, const float* __restrict__ b2)
{
    extern __shared__ char sm[];
    const uint32_t smb = smem_u32(sm);
    const int tid  = threadIdx.x;
    const int wid  = tid >> 5;
    const int lane = tid & 31;
    const int wm   = wid & 3;         // rows 32*wm..32*wm+31
    const int wn   = wid >> 2;        // 0..3
    const int q    = lane & 3;        // col pair within fragment
    const int rb   = lane >> 2;       // row base within fragment
    const int base = blockIdx.x * TILE_M;

    // biases, sp ids
    if (tid < 64)  ((float*)(sm + S_B1))[tid] = b1[tid];
    if (tid < 256) ((float*)(sm + S_B2))[tid] = b2[tid];
    if (tid < 128) ((int*)(sm + S_SPS))[tid] = idx10[base + tid];

    // x tile: load f32, split -> bf16 hi/lo, store swizzled
    for (int i = tid; i < TILE_M * 32; i += 512) {
        int p = i >> 5, c4 = i & 31;
        int k = c4 * 4;
        float4 v = ((const float4*)x)[(base + p) * 32 + c4];
        __nv_bfloat16 h0 = __float2bfloat16_rn(v.x), h1 = __float2bfloat16_rn(v.y);
        __nv_bfloat16 h2 = __float2bfloat16_rn(v.z), h3 = __float2bfloat16_rn(v.w);
        uint2 hi = make_uint2(pack_bf2(v.x, v.y), pack_bf2(v.z, v.w));
        uint2 lo = make_uint2(pack_bf2(v.x - __bfloat162float(h0), v.y - __bfloat162float(h1)),
                              pack_bf2(v.z - __bfloat162float(h2), v.w - __bfloat162float(h3)));
        uint32_t off = off256((uint32_t)p, (uint32_t)k);
        *(uint2*)(sm + S_XHI + off) = hi;
        *(uint2*)(sm + S_XLO + off) = lo;
    }
    __syncthreads();

    const int arow = (lane & 15);
    const int acol8 = (lane >> 4) * 8;

    // ================= layer 1 (A double-buffered over ks, B streamed) =================
    float acc[2][2][4];   // [mt][nth][4]
    #pragma unroll
    for (int mt = 0; mt < 2; mt++)
        #pragma unroll
        for (int nth = 0; nth < 2; nth++)
            #pragma unroll
            for (int j = 0; j < 4; j++) acc[mt][nth][j] = 0.f;

    {
        uint32_t ah[2][2][4], al[2][2][4];   // [buf][mt]
        #pragma unroll
        for (int mt = 0; mt < 2; mt++) {
            uint32_t o = off256((uint32_t)(32*wm + 16*mt + arow), (uint32_t)(0 + acol8));
            ldsm4(ah[0][mt], smb + S_XHI + o);
            ldsm4(al[0][mt], smb + S_XLO + o);
        }
        #pragma unroll
        for (int ks = 0; ks < 8; ks++) {
            const int cur = ks & 1;
            if (ks < 7) {
                const int nxt = cur ^ 1;
                #pragma unroll
                for (int mt = 0; mt < 2; mt++) {
                    uint32_t o = off256((uint32_t)(32*wm + 16*mt + arow),
                                        (uint32_t)(16*(ks + 1) + acol8));
                    ldsm4(ah[nxt][mt], smb + S_XHI + o);
                    ldsm4(al[nxt][mt], smb + S_XLO + o);
                }
            }
            #pragma unroll
            for (int nth = 0; nth < 2; nth++) {
                const uint4 f = __ldg(&g_w1f[((wn*2 + nth)*8 + ks)*32 + lane]);
                #pragma unroll
                for (int mt = 0; mt < 2; mt++) {
                    mma_bf16(acc[mt][nth], ah[cur][mt], f.x, f.y);   // hi*hi
                    mma_bf16(acc[mt][nth], al[cur][mt], f.x, f.y);   // lo*hi
                    mma_bf16(acc[mt][nth], ah[cur][mt], f.z, f.w);   // hi*lo
                }
            }
        }
    }

    // epilogue 1: bias + relu -> bf16 hi/lo into smem H (swizzled)
    {
        const float* b1s = (const float*)(sm + S_B1);
        #pragma unroll
        for (int nth = 0; nth < 2; nth++) {
            const int col = 16*wn + 8*nth + 2*q;
            const float bia0 = b1s[col], bia1 = b1s[col + 1];
            #pragma unroll
            for (int mt = 0; mt < 2; mt++) {
                int r1 = 32*wm + 16*mt + rb, r2 = r1 + 8;
                float v00 = fmaxf(acc[mt][nth][0] + bia0, 0.f);
                float v01 = fmaxf(acc[mt][nth][1] + bia1, 0.f);
                float v10 = fmaxf(acc[mt][nth][2] + bia0, 0.f);
                float v11 = fmaxf(acc[mt][nth][3] + bia1, 0.f);
                __nv_bfloat16 h00 = __float2bfloat16_rn(v00), h01 = __float2bfloat16_rn(v01);
                __nv_bfloat16 h10 = __float2bfloat16_rn(v10), h11 = __float2bfloat16_rn(v11);
                uint32_t o1 = off128((uint32_t)r1, (uint32_t)col);
                uint32_t o2 = off128((uint32_t)r2, (uint32_t)col);
                *(uint32_t*)(sm + S_HHI + o1) = pack_bf2(v00, v01);
                *(uint32_t*)(sm + S_HHI + o2) = pack_bf2(v10, v11);
                *(uint32_t*)(sm + S_HLO + o1) = pack_bf2(v00 - __bfloat162float(h00),
                                                         v01 - __bfloat162float(h01));
                *(uint32_t*)(sm + S_HLO + o2) = pack_bf2(v10 - __bfloat162float(h10),
                                                         v11 - __bfloat162float(h11));
            }
        }
    }
    __syncthreads();

    // sp ids of this thread's fragment rows (warp's 32-row quarter)
    const int* sps = (const int*)(sm + S_SPS);
    int sprow[4];
    #pragma unroll
    for (int mt = 0; mt < 2; mt++) {
        sprow[2*mt]     = sps[32*wm + 16*mt + rb];
        sprow[2*mt + 1] = sps[32*wm + 16*mt + rb + 8];
    }

    // ================= layer 2: cols 64wn..+63, single pass (A ldsm once per ks) =================
    float a2[8][2][4];   // [nt][mt][4] = 64 regs
    #pragma unroll
    for (int nt = 0; nt < 8; nt++)
        #pragma unroll
        for (int mt = 0; mt < 2; mt++)
            #pragma unroll
            for (int j = 0; j < 4; j++) a2[nt][mt][j] = 0.f;

    {
        uint32_t ah[2][2][4], al[2][2][4];   // [buf][mt]
        #pragma unroll
        for (int mt = 0; mt < 2; mt++) {
            uint32_t o = off128((uint32_t)(32*wm + 16*mt + arow), (uint32_t)(0 + acol8));
            ldsm4(ah[0][mt], smb + S_HHI + o);
            ldsm4(al[0][mt], smb + S_HLO + o);
        }
        #pragma unroll
        for (int ks = 0; ks < 4; ks++) {
            const int cur = ks & 1;
            if (ks < 3) {
                const int nxt = cur ^ 1;
                #pragma unroll
                for (int mt = 0; mt < 2; mt++) {
                    uint32_t o = off128((uint32_t)(32*wm + 16*mt + arow),
                                        (uint32_t)(16*(ks + 1) + acol8));
                    ldsm4(ah[nxt][mt], smb + S_HHI + o);
                    ldsm4(al[nxt][mt], smb + S_HLO + o);
                }
            }
            #pragma unroll
            for (int nt = 0; nt < 8; nt++) {
                const uint4 f = __ldg(&g_w2f[((wn*8 + nt)*4 + ks)*32 + lane]);
                #pragma unroll
                for (int mt = 0; mt < 2; mt++) {
                    mma_bf16(a2[nt][mt], ah[cur][mt], f.x, f.y);
                    mma_bf16(a2[nt][mt], al[cur][mt], f.x, f.y);
                    mma_bf16(a2[nt][mt], ah[cur][mt], f.z, f.w);
                }
            }
        }
    }

    // epilogue 2: bias + relu + segmented max (rows strictly increasing) -> atomicMax
    {
        const float* b2s = (const float*)(sm + S_B2);
        #pragma unroll
        for (int nt = 0; nt < 8; nt++) {
            int colb = 64*wn + 8*nt + 2*q;
            #pragma unroll
            for (int c01 = 0; c01 < 2; c01++) {
                int col = colb + c01;
                float bias = b2s[col];
                int cursp = sprow[0];
                float cur = -1.f;
                #pragma unroll
                for (int mt = 0; mt < 2; mt++) {
                    #pragma unroll
                    for (int rr = 0; rr < 2; rr++) {
                        float v = fmaxf(a2[nt][mt][c01 + 2*rr] + bias, 0.f);
                        int sp = sprow[2*mt + rr];
                        if (sp != cursp) {
                            atomicMax(&g_tok[cursp * EMBED + col], __float_as_int(cur));
                            cursp = sp; cur = v;
                        } else {
                            cur = fmaxf(cur, v);
                        }
                    }
                }
                atomicMax(&g_tok[cursp * EMBED + col], __float_as_int(cur));
            }
        }
    }
}

// ---------------- scatter ----------------
__global__ void k_scatter(const int* __restrict__ idx21,
                          const void* __restrict__ is_masked,
                          float* __restrict__ out)
{
    const int sp = blockIdx.x;
    __shared__ int s_off;
    if (threadIdx.x == 0) {
        const int mode = g_mask_is_i32;
        const int* mi = (const int*)is_masked;
        const unsigned char* mb = (const unsigned char*)is_masked;
        int g = idx21[sp];
        int lo = 0, hi = sp;
        while (lo < hi) { int mid = (lo + hi) >> 1; if (idx21[mid] < g) lo = mid + 1; else hi = mid; }
        bool me = mode ? (mi[sp] != 0) : (mb[sp] != 0);
        int rank = 0;
        for (int j = lo; j < sp; j++) {
            bool fj = mode ? (mi[j] != 0) : (mb[j] != 0);
            rank += (fj == me);
        }
        int b = me ? (NUM_SP2 * PAD_LIMIT * EMBED) : 0;
        s_off = b + (g * PAD_LIMIT + rank) * EMBED;
    }
    __syncthreads();
    float4*       dst = (float4*)(out + s_off);
    const float4* src = (const float4*)((const float*)g_tok + sp * EMBED);
    dst[threadIdx.x] = src[threadIdx.x];
}

// ---------------- launch ----------------
extern "C" void kernel_launch(void* const* d_in, const int* in_sizes, int n_in,
                              void* d_out, int out_size) {
    const float* x     = (const float*)d_in[0];
    const int*   idx10 = (const int*)d_in[1];
    const int*   idx21 = (const int*)d_in[2];
    const void*  msk   = (const void*)d_in[3];
    const float* W1    = (const float*)d_in[4];
    const float* b1    = (const float*)d_in[5];
    const float* W2    = (const float*)d_in[6];
    const float* b2    = (const float*)d_in[7];
    float* out = (float*)d_out;

    cudaFuncSetAttribute(k_main, cudaFuncAttributeMaxDynamicSharedMemorySize, SMEM_TOTAL);

    cudaMemsetAsync(out, 0, (size_t)out_size * sizeof(float));
    k_zero_tok<<<(NUM_SP * EMBED + 255) / 256, 256>>>();
    k_prep_w<<<32, 256>>>(W1, W2, (const int*)msk);
    k_main<<<N_TILES, 512, SMEM_TOTAL>>>(x, idx10, b1, b2);
    k_scatter<<<NUM_SP, 64>>>(idx21, msk, out);
}

// round 8
// speedup vs baseline: 3.0026x; 1.0088x over previous
#include <cuda_runtime.h>
#include <cuda_bf16.h>
#include <stdint.h>

#define N_POINTS 262144
#define SP_FEAT  128
#define HIDDEN   64
#define EMBED    256
#define NUM_SP   4096
#define NUM_SP2  256
#define PAD_LIMIT 64
#define TILE_M   128
#define N_TILES  (N_POINTS / TILE_M)   // 2048
#define GRID_MAIN 148

// ---------------- device scratch ----------------
__device__ int g_tok[NUM_SP * EMBED];          // float bits, values >= 0
__device__ int g_mask_is_i32;
// prepacked B fragments (mma.m16n8k16 layout), uint4 = {hi_reg0, hi_reg1, lo_reg0, lo_reg1}
// layout: [n8][ks][lane] with n8 = n/8
__device__ __align__(16) uint4 g_w1f[8 * 8 * 32];    // (8 KB)
__device__ __align__(16) uint4 g_w2f[32 * 4 * 32];   // (64 KB)

// ---------------- helpers ----------------
__device__ __forceinline__ uint32_t smem_u32(const void* p) {
    uint32_t a;
    asm("{ .reg .u64 t; cvta.to.shared.u64 t, %1; cvt.u32.u64 %0, t; }" : "=r"(a) : "l"(p));
    return a;
}
__device__ __forceinline__ uint32_t off256(uint32_t row, uint32_t k) {
    return row * 256u + (((k >> 3) ^ (row & 7u)) << 4) + (k & 7u) * 2u;
}
__device__ __forceinline__ uint32_t off128(uint32_t row, uint32_t k) {
    return row * 128u + ((((k >> 3) ^ (row & 7u)) & 7u) << 4) + (k & 7u) * 2u;
}
__device__ __forceinline__ uint32_t pack_bf2(float a, float b) {
    __nv_bfloat162 t = __floats2bfloat162_rn(a, b);
    return *(uint32_t*)&t;
}
__device__ __forceinline__ void ldsm4(uint32_t r[4], uint32_t addr) {
    asm volatile("ldmatrix.sync.aligned.m8n8.x4.shared.b16 {%0,%1,%2,%3}, [%4];"
                 : "=r"(r[0]), "=r"(r[1]), "=r"(r[2]), "=r"(r[3]) : "r"(addr));
}
__device__ __forceinline__ void mma_bf16(float c[4], const uint32_t a[4],
                                         uint32_t b0, uint32_t b1) {
    asm volatile("mma.sync.aligned.m16n8k16.row.col.f32.bf16.bf16.f32 "
                 "{%0,%1,%2,%3}, {%4,%5,%6,%7}, {%8,%9}, {%0,%1,%2,%3};"
                 : "+f"(c[0]), "+f"(c[1]), "+f"(c[2]), "+f"(c[3])
                 : "r"(a[0]), "r"(a[1]), "r"(a[2]), "r"(a[3]), "r"(b0), "r"(b1));
}
__device__ __forceinline__ void cp_async16(uint32_t dst, const void* src) {
    asm volatile("cp.async.cg.shared.global [%0], [%1], 16;" :: "r"(dst), "l"(src));
}
#define CP_COMMIT() asm volatile("cp.async.commit_group;" ::: "memory")
#define CP_WAIT0()  asm volatile("cp.async.wait_group 0;"  ::: "memory")

// ---------------- smem layout (dynamic) ----------------
#define S_XSTAGE 0          // 128x128 f32 staging (65536)
#define S_XHI    65536      // 128x128 bf16, 256B rows, swizzled (32768)
#define S_XLO    98304
#define S_HHI    131072     // 128x64 bf16, 128B rows, swizzled (16384)
#define S_HLO    147456
#define S_SPS    163840     // 128 ints
#define S_B1     164352     // 64 f32
#define S_B2     164608     // 256 f32
#define SMEM_TOTAL 165632

// ---------------- small kernels ----------------
__global__ void k_zero_tok() {
    int i = blockIdx.x * blockDim.x + threadIdx.x;
    if (i < NUM_SP * EMBED) g_tok[i] = 0;
}

// Prepack B fragments + detect is_masked dtype (block 0).
__global__ void k_prep_w(const float* __restrict__ W1, const float* __restrict__ W2,
                         const int* __restrict__ msk) {
    int i = blockIdx.x * blockDim.x + threadIdx.x;     // 8192 threads
    if (blockIdx.x == 0) {
        __shared__ int bad;
        if (threadIdx.x == 0) bad = 0;
        __syncthreads();
        for (int j = threadIdx.x; j < 1024; j += blockDim.x)
            if ((unsigned)msk[j] > 1u) atomicOr(&bad, 1);
        __syncthreads();
        if (threadIdx.x == 0) g_mask_is_i32 = bad ? 0 : 1;
    }
    if (i < 2048) {                                     // layer1: [n8(8)][ks(8)][lane]
        int lane = i & 31, ks = (i >> 5) & 7, n8 = i >> 8;
        int n  = 8 * n8 + (lane >> 2);
        int k0 = 16 * ks + 2 * (lane & 3);
        float v00 = W1[k0 * HIDDEN + n],       v01 = W1[(k0 + 1) * HIDDEN + n];
        float v10 = W1[(k0 + 8) * HIDDEN + n], v11 = W1[(k0 + 9) * HIDDEN + n];
        __nv_bfloat16 h00 = __float2bfloat16_rn(v00), h01 = __float2bfloat16_rn(v01);
        __nv_bfloat16 h10 = __float2bfloat16_rn(v10), h11 = __float2bfloat16_rn(v11);
        uint4 f;
        f.x = pack_bf2(v00, v01);
        f.y = pack_bf2(v10, v11);
        f.z = pack_bf2(v00 - __bfloat162float(h00), v01 - __bfloat162float(h01));
        f.w = pack_bf2(v10 - __bfloat162float(h10), v11 - __bfloat162float(h11));
        g_w1f[i] = f;
    } else if (i < 2048 + 4096) {                       // layer2: [n8(32)][ks(4)][lane]
        int j = i - 2048;
        int lane = j & 31, ks = (j >> 5) & 3, n8 = j >> 7;
        int n  = 8 * n8 + (lane >> 2);
        int k0 = 16 * ks + 2 * (lane & 3);
        float v00 = W2[k0 * EMBED + n],       v01 = W2[(k0 + 1) * EMBED + n];
        float v10 = W2[(k0 + 8) * EMBED + n], v11 = W2[(k0 + 9) * EMBED + n];
        __nv_bfloat16 h00 = __float2bfloat16_rn(v00), h01 = __float2bfloat16_rn(v01);
        __nv_bfloat16 h10 = __float2bfloat16_rn(v10), h11 = __float2bfloat16_rn(v11);
        uint4 f;
        f.x = pack_bf2(v00, v01);
        f.y = pack_bf2(v10, v11);
        f.z = pack_bf2(v00 - __bfloat162float(h00), v01 - __bfloat162float(h01));
        f.w = pack_bf2(v10 - __bfloat162float(h10), v11 - __bfloat162float(h11));
        g_w2f[j] = f;
    }
}

// ---------------- persistent main kernel ----------------
// warp = (wm 0..7, wn 0..1): rows 16wm..+15; layer1 cols 32wn..+31; layer2 cols 128wn..+127
__global__ __launch_bounds__(512, 1)
void k_main(const float* __restrict__ x, const int* __restrict__ idx10,
            const float* __restrict__ b1, const float* __restrict__ b2)
{
    extern __shared__ char sm[];
    const uint32_t smb = smem_u32(sm);
    const int tid  = threadIdx.x;
    const int wid  = tid >> 5;
    const int lane = tid & 31;
    const int wm   = wid & 7;         // rows 16*wm..16*wm+15
    const int wn   = wid >> 3;        // 0..1
    const int q    = lane & 3;
    const int rb   = lane >> 2;
    const int arow  = lane & 15;
    const int acol8 = (lane >> 4) * 8;

    if (tid < 64)  ((float*)(sm + S_B1))[tid] = b1[tid];
    if (tid < 256) ((float*)(sm + S_B2))[tid] = b2[tid];

    // prefetch first tile's x into staging
    int t = blockIdx.x;
    {
        const float* src = x + (size_t)t * (TILE_M * 32) * 4;
        #pragma unroll
        for (int j = 0; j < 8; j++) {
            int idx = tid + j * 512;
            cp_async16(smb + S_XSTAGE + idx * 16, src + idx * 4);
        }
    }
    CP_COMMIT();

    for (; t < N_TILES; t += GRID_MAIN) {
        CP_WAIT0();
        __syncthreads();                       // staged x visible; prev-iter smem readers done

        if (tid < 128) ((int*)(sm + S_SPS))[tid] = idx10[t * TILE_M + tid];

        // convert staged f32 -> bf16 hi/lo swizzled
        for (int i = tid; i < TILE_M * 32; i += 512) {
            int p = i >> 5, c4 = i & 31;
            int k = c4 * 4;
            float4 v = ((const float4*)(sm + S_XSTAGE))[i];
            __nv_bfloat16 h0 = __float2bfloat16_rn(v.x), h1 = __float2bfloat16_rn(v.y);
            __nv_bfloat16 h2 = __float2bfloat16_rn(v.z), h3 = __float2bfloat16_rn(v.w);
            uint2 hi = make_uint2(pack_bf2(v.x, v.y), pack_bf2(v.z, v.w));
            uint2 lo = make_uint2(pack_bf2(v.x - __bfloat162float(h0), v.y - __bfloat162float(h1)),
                                  pack_bf2(v.z - __bfloat162float(h2), v.w - __bfloat162float(h3)));
            uint32_t off = off256((uint32_t)p, (uint32_t)k);
            *(uint2*)(sm + S_XHI + off) = hi;
            *(uint2*)(sm + S_XLO + off) = lo;
        }
        __syncthreads();                       // staging consumed; XHI/XLO + sps ready

        // prefetch next tile
        {
            int tn = t + GRID_MAIN;
            if (tn < N_TILES) {
                const float* src = x + (size_t)tn * (TILE_M * 32) * 4;
                #pragma unroll
                for (int j = 0; j < 8; j++) {
                    int idx = tid + j * 512;
                    cp_async16(smb + S_XSTAGE + idx * 16, src + idx * 4);
                }
            }
            CP_COMMIT();
        }

        // ================= layer 1: rows 16wm..+15, cols 32wn..+31 =================
        float acc[4][4];
        #pragma unroll
        for (int nth = 0; nth < 4; nth++)
            #pragma unroll
            for (int j = 0; j < 4; j++) acc[nth][j] = 0.f;

        {
            uint32_t ah[2][4], al[2][4];
            {
                uint32_t o = off256((uint32_t)(16*wm + arow), (uint32_t)acol8);
                ldsm4(ah[0], smb + S_XHI + o);
                ldsm4(al[0], smb + S_XLO + o);
            }
            #pragma unroll
            for (int ks = 0; ks < 8; ks++) {
                const int cur = ks & 1;
                if (ks < 7) {
                    uint32_t o = off256((uint32_t)(16*wm + arow),
                                        (uint32_t)(16*(ks + 1) + acol8));
                    ldsm4(ah[cur ^ 1], smb + S_XHI + o);
                    ldsm4(al[cur ^ 1], smb + S_XLO + o);
                }
                #pragma unroll
                for (int nth = 0; nth < 4; nth++) {
                    const uint4 f = __ldg(&g_w1f[((4*wn + nth)*8 + ks)*32 + lane]);
                    mma_bf16(acc[nth], ah[cur], f.x, f.y);   // hi*hi
                    mma_bf16(acc[nth], al[cur], f.x, f.y);   // lo*hi
                    mma_bf16(acc[nth], ah[cur], f.z, f.w);   // hi*lo
                }
            }
        }

        // epilogue 1: bias + relu -> bf16 hi/lo into smem H
        {
            const float* b1s = (const float*)(sm + S_B1);
            #pragma unroll
            for (int nth = 0; nth < 4; nth++) {
                const int col = 32*wn + 8*nth + 2*q;
                const float bia0 = b1s[col], bia1 = b1s[col + 1];
                int r1 = 16*wm + rb, r2 = r1 + 8;
                float v00 = fmaxf(acc[nth][0] + bia0, 0.f);
                float v01 = fmaxf(acc[nth][1] + bia1, 0.f);
                float v10 = fmaxf(acc[nth][2] + bia0, 0.f);
                float v11 = fmaxf(acc[nth][3] + bia1, 0.f);
                __nv_bfloat16 h00 = __float2bfloat16_rn(v00), h01 = __float2bfloat16_rn(v01);
                __nv_bfloat16 h10 = __float2bfloat16_rn(v10), h11 = __float2bfloat16_rn(v11);
                uint32_t o1 = off128((uint32_t)r1, (uint32_t)col);
                uint32_t o2 = off128((uint32_t)r2, (uint32_t)col);
                *(uint32_t*)(sm + S_HHI + o1) = pack_bf2(v00, v01);
                *(uint32_t*)(sm + S_HHI + o2) = pack_bf2(v10, v11);
                *(uint32_t*)(sm + S_HLO + o1) = pack_bf2(v00 - __bfloat162float(h00),
                                                         v01 - __bfloat162float(h01));
                *(uint32_t*)(sm + S_HLO + o2) = pack_bf2(v10 - __bfloat162float(h10),
                                                         v11 - __bfloat162float(h11));
            }
        }
        __syncthreads();

        // sp ids of this thread's fragment rows
        const int* sps = (const int*)(sm + S_SPS);
        const int sp0 = sps[16*wm + rb];
        const int sp1 = sps[16*wm + rb + 8];

        // ================= layer 2: rows 16wm..+15, cols 128wn..+127 =================
        float a2[16][4];
        #pragma unroll
        for (int nt = 0; nt < 16; nt++)
            #pragma unroll
            for (int j = 0; j < 4; j++) a2[nt][j] = 0.f;

        {
            uint32_t ah[2][4], al[2][4];
            {
                uint32_t o = off128((uint32_t)(16*wm + arow), (uint32_t)acol8);
                ldsm4(ah[0], smb + S_HHI + o);
                ldsm4(al[0], smb + S_HLO + o);
            }
            #pragma unroll
            for (int ks = 0; ks < 4; ks++) {
                const int cur = ks & 1;
                if (ks < 3) {
                    uint32_t o = off128((uint32_t)(16*wm + arow),
                                        (uint32_t)(16*(ks + 1) + acol8));
                    ldsm4(ah[cur ^ 1], smb + S_HHI + o);
                    ldsm4(al[cur ^ 1], smb + S_HLO + o);
                }
                #pragma unroll
                for (int nt = 0; nt < 16; nt++) {
                    const uint4 f = __ldg(&g_w2f[((16*wn + nt)*4 + ks)*32 + lane]);
                    mma_bf16(a2[nt], ah[cur], f.x, f.y);
                    mma_bf16(a2[nt], al[cur], f.x, f.y);
                    mma_bf16(a2[nt], ah[cur], f.z, f.w);
                }
            }
        }

        // epilogue 2: bias + relu + 2-row segmented max -> atomicMax
        {
            const float* b2s = (const float*)(sm + S_B2);
            #pragma unroll
            for (int nt = 0; nt < 16; nt++) {
                int colb = 128*wn + 8*nt + 2*q;
                #pragma unroll
                for (int c01 = 0; c01 < 2; c01++) {
                    int col = colb + c01;
                    float bias = b2s[col];
                    float v0 = fmaxf(a2[nt][c01]     + bias, 0.f);
                    float v1 = fmaxf(a2[nt][c01 + 2] + bias, 0.f);
                    if (sp0 == sp1) {
                        atomicMax(&g_tok[sp0 * EMBED + col],
                                  __float_as_int(fmaxf(v0, v1)));
                    } else {
                        atomicMax(&g_tok[sp0 * EMBED + col], __float_as_int(v0));
                        atomicMax(&g_tok[sp1 * EMBED + col], __float_as_int(v1));
                    }
                }
            }
        }
        // loop-top CP_WAIT0 + __syncthreads orders next-iter smem writes after epi2 reads
    }
}

// ---------------- scatter ----------------
__global__ void k_scatter(const int* __restrict__ idx21,
                          const void* __restrict__ is_masked,
                          float* __restrict__ out)
{
    const int sp = blockIdx.x;
    __shared__ int s_off;
    if (threadIdx.x == 0) {
        const int mode = g_mask_is_i32;
        const int* mi = (const int*)is_masked;
        const unsigned char* mb = (const unsigned char*)is_masked;
        int g = idx21[sp];
        int lo = 0, hi = sp;
        while (lo < hi) { int mid = (lo + hi) >> 1; if (idx21[mid] < g) lo = mid + 1; else hi = mid; }
        bool me = mode ? (mi[sp] != 0) : (mb[sp] != 0);
        int rank = 0;
        for (int j = lo; j < sp; j++) {
            bool fj = mode ? (mi[j] != 0) : (mb[j] != 0);
            rank += (fj == me);
        }
        int b = me ? (NUM_SP2 * PAD_LIMIT * EMBED) : 0;
        s_off = b + (g * PAD_LIMIT + rank) * EMBED;
    }
    __syncthreads();
    float4*       dst = (float4*)(out + s_off);
    const float4* src = (const float4*)((const float*)g_tok + sp * EMBED);
    dst[threadIdx.x] = src[threadIdx.x];
}

// ---------------- launch ----------------
extern "C" void kernel_launch(void* const* d_in, const int* in_sizes, int n_in,
                              void* d_out, int out_size) {
    const float* x     = (const float*)d_in[0];
    const int*   idx10 = (const int*)d_in[1];
    const int*   idx21 = (const int*)d_in[2];
    const void*  msk   = (const void*)d_in[3];
    const float* W1    = (const float*)d_in[4];
    const float* b1    = (const float*)d_in[5];
    const float* W2    = (const float*)d_in[6];
    const float* b2    = (const float*)d_in[7];
    float* out = (float*)d_out;

    cudaFuncSetAttribute(k_main, cudaFuncAttributeMaxDynamicSharedMemorySize, SMEM_TOTAL);

    cudaMemsetAsync(out, 0, (size_t)out_size * sizeof(float));
    k_zero_tok<<<(NUM_SP * EMBED + 255) / 256, 256>>>();
    k_prep_w<<<32, 256>>>(W1, W2, (const int*)msk);
    k_main<<<GRID_MAIN, 512, SMEM_TOTAL>>>(x, idx10, b1, b2);
    k_scatter<<<NUM_SP, 64>>>(idx21, msk, out);
}